// round 9
// baseline (speedup 1.0000x reference)
#include <cuda_runtime.h>
#include <math.h>

#define BATCH 2
#define NCH   8
#define HI    256
#define HS    64
#define HW    4096
#define CDIM  256
#define LOG2E 1.4426950408889634f

typedef unsigned long long ull;

// ---------------- scratch ----------------------------------------------------
__device__ float  g_normc[2][BATCH][HW][CDIM];   // normalized, class-compacted
__device__ float4 g_colP[2][BATCH][HW];          // colors by pixel
__device__ float4 g_colc[2][BATCH][HW];          // colors compacted
__device__ int    g_lab[2][BATCH][HW];
__device__ int    g_slot[2][BATCH][HW];          // local slot within class
__device__ int    g_list[2][BATCH][NCH][HW];     // pixel list per class
__device__ int    g_cnt[2][BATCH][NCH];
__device__ int    g_off[2][BATCH][NCH];          // class prefix offsets
__device__ float  g_mean[2][BATCH][NCH][CDIM];
__device__ float4 g_part[2][BATCH][NCH][HW];     // per-half (x,y,z,l) partials
__device__ float  g_canvas[BATCH][3][HW];

__device__ __forceinline__ void fma2(ull &d, ull a, ull b) {
    asm("fma.rn.f32x2 %0, %1, %2, %0;" : "+l"(d) : "l"(a), "l"(b));
}
__device__ __forceinline__ float2 unpk(ull v) {
    float2 r; asm("mov.b64 {%0,%1}, %2;" : "=f"(r.x), "=f"(r.y) : "l"(v)); return r;
}
__device__ __forceinline__ float ex2(float x) {
    float r; asm("ex2.approx.f32 %0, %1;" : "=f"(r) : "f"(x)); return r;
}
__device__ __forceinline__ void cpa16(unsigned smem, const void* g) {
    asm volatile("cp.async.cg.shared.global [%0], [%1], 16;" :: "r"(smem), "l"(g));
}

// ---------------- K1: colors (bilinear down) + zero canvas -------------------
__global__ void k_pre(const float* __restrict__ trgb, const float* __restrict__ srgb)
{
    int pix = blockIdx.x * blockDim.x + threadIdx.x;
    int b = blockIdx.y;
    if (pix >= HW) return;
    int y4 = (pix >> 6) * 4, x4 = (pix & 63) * 4;
    float tc[3], sc[3];
#pragma unroll
    for (int ch = 0; ch < 3; ch++) {
        size_t base = ((size_t)(b * 3 + ch) * HI + (y4 + 1)) * HI + (x4 + 1);
        tc[ch] = 0.25f * (trgb[base] + trgb[base + 1] + trgb[base + HI] + trgb[base + HI + 1]);
        sc[ch] = 0.25f * (srgb[base] + srgb[base + 1] + srgb[base + HI] + srgb[base + HI + 1]);
    }
    g_colP[0][b][pix] = make_float4(tc[0], tc[1], tc[2], 0.f);
    g_colP[1][b][pix] = make_float4(sc[0], sc[1], sc[2], 0.f);
    g_canvas[b][0][pix] = 0.f;
    g_canvas[b][1][pix] = 0.f;
    g_canvas[b][2][pix] = 0.f;
}

// ---------------- K2: labels + compaction (lists, slots, counts, offsets) ----
__global__ void k_compact(const float* __restrict__ toh, const float* __restrict__ soh)
{
    __shared__ int LAB[HW];
    __shared__ int cnt_sm[NCH];
    int side = blockIdx.x >> 1, b = blockIdx.x & 1;
    const float* __restrict__ oh = side ? soh : toh;
    int tid = threadIdx.x;

    for (int pix = tid; pix < HW; pix += 256) {
        int y4 = (pix >> 6) * 4, x4 = (pix & 63) * 4;
        int l = 0;
#pragma unroll
        for (int ch = 0; ch < NCH; ch++)
            if (oh[((size_t)(b * NCH + ch) * HI + y4) * HI + x4] > 0.f) l = ch;
        LAB[pix] = l;
        g_lab[side][b][pix] = l;
    }
    __syncthreads();

    int cls = tid >> 5, lane = tid & 31;
    const int4* __restrict__ lp = (const int4*)LAB;
    int* __restrict__ lst = g_list[side][b][cls];
    int* __restrict__ slt = g_slot[side][b];
    int base = 0;
    for (int r = 0; r < HW / 128; r++) {
        int4 v = lp[r * 32 + lane];
        int vv[4] = {v.x, v.y, v.z, v.w};
#pragma unroll
        for (int e = 0; e < 4; e++) {
            bool m = (vv[e] == cls);
            unsigned bal = __ballot_sync(0xffffffffu, m);
            if (m) {
                int s = base + __popc(bal & ((1u << lane) - 1u));
                int pp = (r * 32 + lane) * 4 + e;
                lst[s] = pp;
                slt[pp] = s;
            }
            base += __popc(bal);
        }
    }
    if (lane == 0) { g_cnt[side][b][cls] = base; cnt_sm[cls] = base; }
    __syncthreads();
    if (tid == 0) {
        int off = 0;
#pragma unroll
        for (int c = 0; c < NCH; c++) { g_off[side][b][c] = off; off += cnt_sm[c]; }
    }
}

// ---------------- K3: per-class channel means (predicated accumulate) --------
__global__ void k_mean(const float* __restrict__ tfeat, const float* __restrict__ sfeat)
{
    __shared__ int lab_sm[HW];
    int b = blockIdx.y, side = blockIdx.z;
    const float* __restrict__ in = side ? sfeat : tfeat;
    int tid = threadIdx.x;
    for (int i = tid; i < HW / 4; i += 256)
        ((int4*)lab_sm)[i] = ((const int4*)g_lab[side][b])[i];
    __syncthreads();
    int ch = blockIdx.x * 8 + (tid >> 5);
    int lane = tid & 31;
    const float4* __restrict__ row = (const float4*)(in + ((size_t)b * CDIM + ch) * HW);
    float acc[7];
#pragma unroll
    for (int c = 0; c < 7; c++) acc[c] = 0.f;
    for (int it = 0; it < HW / 128; it++) {
        int i4 = it * 32 + lane;
        float4 v = row[i4];
        int4 lb = ((const int4*)lab_sm)[i4];
        float vv[4] = {v.x, v.y, v.z, v.w};
        int ll[4] = {lb.x, lb.y, lb.z, lb.w};
#pragma unroll
        for (int e = 0; e < 4; e++)
#pragma unroll
            for (int c = 0; c < 7; c++)
                acc[c] += (ll[e] == c + 1) ? vv[e] : 0.f;
    }
#pragma unroll
    for (int c = 0; c < 7; c++) {
        float s = acc[c];
#pragma unroll
        for (int off = 16; off; off >>= 1) s += __shfl_xor_sync(0xffffffffu, s, off);
        if (lane == 0)
            g_mean[side][b][c + 1][ch] = s / (float)max(g_cnt[side][b][c + 1], 1);
    }
}

// ---------------- K4: transpose + center + normalize + compact (1 smem pass) -
// 256 threads, 32 pixels x 256 ch. Thread p (of 8 per pixel) owns channel
// quads {p, p+8, ..., p+56}: center-phase LDS conflict-free (pad 33),
// scaled values written straight to gmem as float4.
__global__ void k_tn(const float* __restrict__ tfeat, const float* __restrict__ sfeat)
{
    __shared__ float T[CDIM][33];
    __shared__ float MS[NCH][257];
    __shared__ int LB[32], SL[32], OFF[NCH], CNTS[NCH];

    int b = blockIdx.y, side = blockIdx.z;
    int pix0 = blockIdx.x * 32;
    const float* __restrict__ in = side ? sfeat : tfeat;
    int tid = threadIdx.x;

#pragma unroll
    for (int c = 0; c < NCH; c++)
        MS[c][tid] = (c >= 1) ? g_mean[side][b][c][tid] : 0.f;
    if (tid < 32) {
        LB[tid] = g_lab[side][b][pix0 + tid];
        SL[tid] = g_slot[side][b][pix0 + tid];
    }
    if (tid < NCH) {
        OFF[tid] = g_off[side][b][tid];
        CNTS[tid] = g_cnt[side][b][tid];
    }

    int px = tid & 31, cg = tid >> 5;
#pragma unroll
    for (int r = 0; r < 32; r++) {
        int ch = cg * 32 + r;
        T[ch][px] = in[((size_t)b * CDIM + ch) * HW + pix0 + px];
    }
    __syncthreads();

    if (tid < 32 && LB[tid] > 0)
        g_colc[side][b][OFF[LB[tid]] + SL[tid]] = g_colP[side][b][pix0 + tid];

    int px2 = tid >> 3, p = tid & 7;
    int lab = LB[px2];
    float v[32];
    float sq = 0.f;
#pragma unroll
    for (int r = 0; r < 8; r++) {
        int q = p + 8 * r;
#pragma unroll
        for (int j = 0; j < 4; j++) {
            float d = T[4 * q + j][px2] - MS[lab][4 * q + j];
            v[4 * r + j] = d;
            sq += d * d;
        }
    }
    sq += __shfl_xor_sync(0xffffffffu, sq, 1);
    sq += __shfl_xor_sync(0xffffffffu, sq, 2);
    sq += __shfl_xor_sync(0xffffffffu, sq, 4);
    float scale = (CNTS[lab] == 1) ? 1.f : 1.f / fmaxf(sqrtf(sq), 1e-12f);

    if (lab > 0) {
        float4* __restrict__ orow = (float4*)g_normc[side][b][OFF[lab] + SL[px2]];
#pragma unroll
        for (int r = 0; r < 8; r++)
            orow[p + 8 * r] = make_float4(v[4 * r] * scale, v[4 * r + 1] * scale,
                                          v[4 * r + 2] * scale, v[4 * r + 3] * scale);
    }
}

// ---------------- K5: attention (4 warps x 16 targets, 64-src chunks, ------
//                  2 sources/lane, cp.async double-buffered ST) --------------
#define TGTB 64
#define TPW  16
#define PAD  67
#define ST_ONE (64 * PAD * 16)
#define ATTN_SMEM (3 * ST_ONE)

__global__ void __launch_bounds__(128) k_attn()
{
    extern __shared__ unsigned char smem_raw[];
    float4 (*TT4)[PAD] = (float4(*)[PAD])(smem_raw + 2 * ST_ONE);

    int cls  = blockIdx.y + 1;
    int half = blockIdx.z & 1;
    int b    = blockIdx.z >> 1;
    int nt = g_cnt[0][b][cls];
    int t0 = blockIdx.x * TGTB;
    if (t0 >= nt) return;

    int scnt = g_cnt[1][b][cls];
    int srcSide = (scnt < 9) ? 0 : 1;
    int nsAll = g_cnt[srcSide][b][cls];
    int sLo = (nsAll * half) >> 1;
    int sHi = (nsAll * (half + 1)) >> 1;

    const float4* __restrict__ tFeat = (const float4*)g_normc[0][b][g_off[0][b][cls]];
    const float4* __restrict__ sFeat = (const float4*)g_normc[srcSide][b][g_off[srcSide][b][cls]];
    const float4* __restrict__ sCol  = &g_colc[srcSide][b][g_off[srcSide][b][cls]];

    int tid = threadIdx.x, w = tid >> 5, lane = tid & 31;
    unsigned st_u32 = (unsigned)__cvta_generic_to_shared(smem_raw);

    // TT fill: 64 targets x 64 float4, LOG2E folded (regular LDG/STS)
#pragma unroll
    for (int k = 0; k < 32; k++) {
        int idx = tid + 128 * k;
        int row = idx >> 6, q = idx & 63;
        int ti = min(t0 + row, nt - 1);
        float4 f = tFeat[(size_t)ti * 64 + q];
        TT4[q][row] = make_float4(f.x * LOG2E, f.y * LOG2E, f.z * LOG2E, f.w * LOG2E);
    }

    float lv[TPW], xv[TPW], yv[TPW], zv[TPW];
#pragma unroll
    for (int t = 0; t < TPW; t++) { lv[t] = 0.f; xv[t] = 0.f; yv[t] = 0.f; zv[t] = 0.f; }

    // prefetch first chunk into buffer 0
    if (sLo < sHi) {
#pragma unroll
        for (int k = 0; k < 32; k++) {
            int idx = tid + 128 * k;
            int row = idx >> 6, q = idx & 63;
            int si = min(sLo + row, sHi - 1);
            cpa16(st_u32 + (unsigned)((q * PAD + row) * 16),
                  sFeat + (size_t)si * 64 + q);
        }
        asm volatile("cp.async.commit_group;");
    }

    int buf = 0;
    for (int c0 = sLo; c0 < sHi; c0 += 64) {
        asm volatile("cp.async.wait_group 0;");
        __syncthreads();                 // current buffer ready; prev compute done
        if (c0 + 64 < sHi) {
            unsigned dst = st_u32 + (unsigned)((buf ^ 1) * ST_ONE);
#pragma unroll
            for (int k = 0; k < 32; k++) {
                int idx = tid + 128 * k;
                int row = idx >> 6, q = idx & 63;
                int si = min(c0 + 64 + row, sHi - 1);
                cpa16(dst + (unsigned)((q * PAD + row) * 16),
                      sFeat + (size_t)si * 64 + q);
            }
            asm volatile("cp.async.commit_group;");
        }

        int n = sHi - c0;
        bool on0 = lane < n, on1 = lane + 32 < n;
        float4 sc0 = sCol[min(c0 + lane, sHi - 1)];
        float4 sc1 = sCol[min(c0 + 32 + lane, sHi - 1)];

        const float4 (*ST4)[PAD] = (const float4(*)[PAD])(smem_raw + buf * ST_ONE);

        ull d0[TPW], d1[TPW];
#pragma unroll
        for (int t = 0; t < TPW; t++) { d0[t] = 0; d1[t] = 0; }
#pragma unroll 2
        for (int k4 = 0; k4 < 64; k4++) {
            ulonglong2 s0 = *(const ulonglong2*)&ST4[k4][lane];
            ulonglong2 s1 = *(const ulonglong2*)&ST4[k4][lane + 32];
#pragma unroll
            for (int t = 0; t < TPW; t++) {
                ulonglong2 tv = *(const ulonglong2*)&TT4[k4][TPW * w + t];
                fma2(d0[t], s0.x, tv.x);
                fma2(d0[t], s0.y, tv.y);
                fma2(d1[t], s1.x, tv.x);
                fma2(d1[t], s1.y, tv.y);
            }
        }
#pragma unroll
        for (int t = 0; t < TPW; t++) {
            float2 e0 = unpk(d0[t]), e1 = unpk(d1[t]);
            float p0 = on0 ? ex2(e0.x + e0.y) : 0.f;
            float p1 = on1 ? ex2(e1.x + e1.y) : 0.f;
            lv[t] += p0 + p1;
            xv[t] += p0 * sc0.x + p1 * sc1.x;
            yv[t] += p0 * sc0.y + p1 * sc1.y;
            zv[t] += p0 * sc0.z + p1 * sc1.z;
        }
        buf ^= 1;
    }

#pragma unroll
    for (int t = 0; t < TPW; t++) {
        float l = lv[t], x = xv[t], y = yv[t], z = zv[t];
#pragma unroll
        for (int off = 16; off; off >>= 1) {
            l += __shfl_xor_sync(0xffffffffu, l, off);
            x += __shfl_xor_sync(0xffffffffu, x, off);
            y += __shfl_xor_sync(0xffffffffu, y, off);
            z += __shfl_xor_sync(0xffffffffu, z, off);
        }
        int ti = t0 + TPW * w + t;
        if (lane == 0 && ti < nt)
            g_part[half][b][cls][ti] = make_float4(x, y, z, l);
    }
}

// ---------------- K6: combine partials, divide, scatter ----------------------
__global__ void k_fin()
{
    int cls = blockIdx.y + 1, b = blockIdx.z;
    int ti = blockIdx.x * blockDim.x + threadIdx.x;
    int nt = g_cnt[0][b][cls];
    if (ti >= nt) return;
    float4 pa = g_part[0][b][cls][ti];
    float4 pb = g_part[1][b][cls][ti];
    float inv = 1.f / (pa.w + pb.w);
    int tp = g_list[0][b][cls][ti];
    g_canvas[b][0][tp] = (pa.x + pb.x) * inv;
    g_canvas[b][1][tp] = (pa.y + pb.y) * inv;
    g_canvas[b][2][tp] = (pa.z + pb.z) * inv;
}

// ---------------- K7: bilinear 64->256 upsample + clip -----------------------
__global__ void k_up(float* __restrict__ out)
{
    int idx = blockIdx.x * blockDim.x + threadIdx.x;
    if (idx >= BATCH * 3 * HI * HI) return;
    int ox = idx & 255;
    int oy = (idx >> 8) & 255;
    int bc = idx >> 16;
    int c = bc % 3, b = bc / 3;
    float sy = oy * 0.25f - 0.375f;
    float sx = ox * 0.25f - 0.375f;
    int iy = (int)floorf(sy), ix = (int)floorf(sx);
    float wy = sy - (float)iy, wx = sx - (float)ix;
    int ya = max(iy, 0), yb = min(iy + 1, HS - 1);
    int xa = max(ix, 0), xb = min(ix + 1, HS - 1);
    const float* __restrict__ P = g_canvas[b][c];
    float v00 = P[ya * HS + xa], v01 = P[ya * HS + xb];
    float v10 = P[yb * HS + xa], v11 = P[yb * HS + xb];
    float v = (1.f - wy) * ((1.f - wx) * v00 + wx * v01)
            +        wy  * ((1.f - wx) * v10 + wx * v11);
    out[idx] = fminf(fmaxf(v, -1.f), 1.f);
}

// ---------------- launch -----------------------------------------------------
extern "C" void kernel_launch(void* const* d_in, const int* in_sizes, int n_in,
                              void* d_out, int out_size)
{
    const float* src_rgb = (const float*)d_in[0];
    const float* tgt_rgb = (const float*)d_in[1];
    const float* src_oh  = (const float*)d_in[2];
    const float* tgt_oh  = (const float*)d_in[3];
    const float* t_feat  = (const float*)d_in[4];
    const float* s_feat  = (const float*)d_in[5];
    float* out = (float*)d_out;

    cudaFuncSetAttribute(k_attn, cudaFuncAttributeMaxDynamicSharedMemorySize, ATTN_SMEM);

    k_pre<<<dim3(HW / 256, BATCH), 256>>>(tgt_rgb, src_rgb);
    k_compact<<<2 * BATCH, 256>>>(tgt_oh, src_oh);
    k_mean<<<dim3(CDIM / 8, BATCH, 2), 256>>>(t_feat, s_feat);
    k_tn<<<dim3(HW / 32, BATCH, 2), 256>>>(t_feat, s_feat);
    k_attn<<<dim3(HW / TGTB, NCH - 1, 2 * BATCH), 128, ATTN_SMEM>>>();
    k_fin<<<dim3(HW / 256, NCH - 1, BATCH), 256>>>();
    k_up<<<(BATCH * 3 * HI * HI) / 256, 256>>>(out);
}

// round 10
// speedup vs baseline: 1.2209x; 1.2209x over previous
#include <cuda_runtime.h>
#include <math.h>

#define BATCH 2
#define NCH   8
#define HI    256
#define HS    64
#define HW    4096
#define CDIM  256
#define LOG2E 1.4426950408889634f

typedef unsigned long long ull;

// ---------------- scratch ----------------------------------------------------
__device__ float  g_normc[2][BATCH][HW][CDIM];   // normalized, class-compacted
__device__ float4 g_colP[2][BATCH][HW];          // colors by pixel
__device__ float4 g_colc[2][BATCH][HW];          // colors compacted
__device__ int    g_lab[2][BATCH][HW];
__device__ int    g_slot[2][BATCH][HW];          // local slot within class
__device__ int    g_list[2][BATCH][NCH][HW];     // pixel list per class
__device__ int    g_cnt[2][BATCH][NCH];
__device__ int    g_off[2][BATCH][NCH];          // class prefix offsets
__device__ float  g_mean[2][BATCH][NCH][CDIM];
__device__ float4 g_part[2][BATCH][NCH][HW];     // per-half (x,y,z,l) partials
__device__ float  g_canvas[BATCH][3][HW];

__device__ __forceinline__ void fma2(ull &d, ull a, ull b) {
    asm("fma.rn.f32x2 %0, %1, %2, %0;" : "+l"(d) : "l"(a), "l"(b));
}
__device__ __forceinline__ float2 unpk(ull v) {
    float2 r; asm("mov.b64 {%0,%1}, %2;" : "=f"(r.x), "=f"(r.y) : "l"(v)); return r;
}
__device__ __forceinline__ float ex2(float x) {
    float r; asm("ex2.approx.f32 %0, %1;" : "=f"(r) : "f"(x)); return r;
}

// ---------------- K1: colors (bilinear down) + zero canvas -------------------
__global__ void k_pre(const float* __restrict__ trgb, const float* __restrict__ srgb)
{
    int pix = blockIdx.x * blockDim.x + threadIdx.x;
    int b = blockIdx.y;
    if (pix >= HW) return;
    int y4 = (pix >> 6) * 4, x4 = (pix & 63) * 4;
    float tc[3], sc[3];
#pragma unroll
    for (int ch = 0; ch < 3; ch++) {
        size_t base = ((size_t)(b * 3 + ch) * HI + (y4 + 1)) * HI + (x4 + 1);
        tc[ch] = 0.25f * (trgb[base] + trgb[base + 1] + trgb[base + HI] + trgb[base + HI + 1]);
        sc[ch] = 0.25f * (srgb[base] + srgb[base + 1] + srgb[base + HI] + srgb[base + HI + 1]);
    }
    g_colP[0][b][pix] = make_float4(tc[0], tc[1], tc[2], 0.f);
    g_colP[1][b][pix] = make_float4(sc[0], sc[1], sc[2], 0.f);
    g_canvas[b][0][pix] = 0.f;
    g_canvas[b][1][pix] = 0.f;
    g_canvas[b][2][pix] = 0.f;
}

// ---------------- K2: labels + compaction (lists, slots, counts, offsets) ----
__global__ void k_compact(const float* __restrict__ toh, const float* __restrict__ soh)
{
    __shared__ int LAB[HW];
    __shared__ int cnt_sm[NCH];
    int side = blockIdx.x >> 1, b = blockIdx.x & 1;
    const float* __restrict__ oh = side ? soh : toh;
    int tid = threadIdx.x;

    for (int pix = tid; pix < HW; pix += 256) {
        int y4 = (pix >> 6) * 4, x4 = (pix & 63) * 4;
        int l = 0;
#pragma unroll
        for (int ch = 0; ch < NCH; ch++)
            if (oh[((size_t)(b * NCH + ch) * HI + y4) * HI + x4] > 0.f) l = ch;
        LAB[pix] = l;
        g_lab[side][b][pix] = l;
    }
    __syncthreads();

    int cls = tid >> 5, lane = tid & 31;
    const int4* __restrict__ lp = (const int4*)LAB;
    int* __restrict__ lst = g_list[side][b][cls];
    int* __restrict__ slt = g_slot[side][b];
    int base = 0;
    for (int r = 0; r < HW / 128; r++) {
        int4 v = lp[r * 32 + lane];
        int vv[4] = {v.x, v.y, v.z, v.w};
#pragma unroll
        for (int e = 0; e < 4; e++) {
            bool m = (vv[e] == cls);
            unsigned bal = __ballot_sync(0xffffffffu, m);
            if (m) {
                int s = base + __popc(bal & ((1u << lane) - 1u));
                int pp = (r * 32 + lane) * 4 + e;
                lst[s] = pp;
                slt[pp] = s;
            }
            base += __popc(bal);
        }
    }
    if (lane == 0) { g_cnt[side][b][cls] = base; cnt_sm[cls] = base; }
    __syncthreads();
    if (tid == 0) {
        int off = 0;
#pragma unroll
        for (int c = 0; c < NCH; c++) { g_off[side][b][c] = off; off += cnt_sm[c]; }
    }
}

// ---------------- K3: per-class channel means (predicated accumulate) --------
__global__ void k_mean(const float* __restrict__ tfeat, const float* __restrict__ sfeat)
{
    __shared__ int lab_sm[HW];
    int b = blockIdx.y, side = blockIdx.z;
    const float* __restrict__ in = side ? sfeat : tfeat;
    int tid = threadIdx.x;
    for (int i = tid; i < HW / 4; i += 256)
        ((int4*)lab_sm)[i] = ((const int4*)g_lab[side][b])[i];
    __syncthreads();
    int ch = blockIdx.x * 8 + (tid >> 5);
    int lane = tid & 31;
    const float4* __restrict__ row = (const float4*)(in + ((size_t)b * CDIM + ch) * HW);
    float acc[7];
#pragma unroll
    for (int c = 0; c < 7; c++) acc[c] = 0.f;
    for (int it = 0; it < HW / 128; it++) {
        int i4 = it * 32 + lane;
        float4 v = row[i4];
        int4 lb = ((const int4*)lab_sm)[i4];
        float vv[4] = {v.x, v.y, v.z, v.w};
        int ll[4] = {lb.x, lb.y, lb.z, lb.w};
#pragma unroll
        for (int e = 0; e < 4; e++)
#pragma unroll
            for (int c = 0; c < 7; c++)
                acc[c] += (ll[e] == c + 1) ? vv[e] : 0.f;
    }
#pragma unroll
    for (int c = 0; c < 7; c++) {
        float s = acc[c];
#pragma unroll
        for (int off = 16; off; off >>= 1) s += __shfl_xor_sync(0xffffffffu, s, off);
        if (lane == 0)
            g_mean[side][b][c + 1][ch] = s / (float)max(g_cnt[side][b][c + 1], 1);
    }
}

// ---------------- K4: transpose + center + normalize + compact (1 smem pass) -
__global__ void k_tn(const float* __restrict__ tfeat, const float* __restrict__ sfeat)
{
    __shared__ float T[CDIM][33];
    __shared__ float MS[NCH][257];
    __shared__ int LB[32], SL[32], OFF[NCH], CNTS[NCH];

    int b = blockIdx.y, side = blockIdx.z;
    int pix0 = blockIdx.x * 32;
    const float* __restrict__ in = side ? sfeat : tfeat;
    int tid = threadIdx.x;

#pragma unroll
    for (int c = 0; c < NCH; c++)
        MS[c][tid] = (c >= 1) ? g_mean[side][b][c][tid] : 0.f;
    if (tid < 32) {
        LB[tid] = g_lab[side][b][pix0 + tid];
        SL[tid] = g_slot[side][b][pix0 + tid];
    }
    if (tid < NCH) {
        OFF[tid] = g_off[side][b][tid];
        CNTS[tid] = g_cnt[side][b][tid];
    }

    int px = tid & 31, cg = tid >> 5;
#pragma unroll
    for (int r = 0; r < 32; r++) {
        int ch = cg * 32 + r;
        T[ch][px] = in[((size_t)b * CDIM + ch) * HW + pix0 + px];
    }
    __syncthreads();

    if (tid < 32 && LB[tid] > 0)
        g_colc[side][b][OFF[LB[tid]] + SL[tid]] = g_colP[side][b][pix0 + tid];

    int px2 = tid >> 3, p = tid & 7;
    int lab = LB[px2];
    float v[32];
    float sq = 0.f;
#pragma unroll
    for (int r = 0; r < 8; r++) {
        int q = p + 8 * r;
#pragma unroll
        for (int j = 0; j < 4; j++) {
            float d = T[4 * q + j][px2] - MS[lab][4 * q + j];
            v[4 * r + j] = d;
            sq += d * d;
        }
    }
    sq += __shfl_xor_sync(0xffffffffu, sq, 1);
    sq += __shfl_xor_sync(0xffffffffu, sq, 2);
    sq += __shfl_xor_sync(0xffffffffu, sq, 4);
    float scale = (CNTS[lab] == 1) ? 1.f : 1.f / fmaxf(sqrtf(sq), 1e-12f);

    if (lab > 0) {
        float4* __restrict__ orow = (float4*)g_normc[side][b][OFF[lab] + SL[px2]];
#pragma unroll
        for (int r = 0; r < 8; r++)
            orow[p + 8 * r] = make_float4(v[4 * r] * scale, v[4 * r + 1] * scale,
                                          v[4 * r + 2] * scale, v[4 * r + 3] * scale);
    }
}

// ---------------- K5: attention (4 warps x 8 targets, 64-src chunks, --------
//                  2 sources/lane, ~100 KB smem -> 2 blocks/SM) --------------
#define TGTB 32
#define TPW  8
#define SPAD 65
#define TPAD 33
#define ST_BYTES (64 * SPAD * 16)   // 66,560
#define TT_BYTES (64 * TPAD * 16)   // 33,792
#define ATTN_SMEM (ST_BYTES + TT_BYTES + 256)

__global__ void __launch_bounds__(128) k_attn()
{
    extern __shared__ unsigned char smem_raw[];
    float4 (*ST4)[SPAD] = (float4(*)[SPAD])(smem_raw);
    float4 (*TT4)[TPAD] = (float4(*)[TPAD])(smem_raw + ST_BYTES);

    int cls  = blockIdx.y + 1;
    int half = blockIdx.z & 1;
    int b    = blockIdx.z >> 1;
    int nt = g_cnt[0][b][cls];
    int t0 = blockIdx.x * TGTB;
    if (t0 >= nt) return;

    int scnt = g_cnt[1][b][cls];
    int srcSide = (scnt < 9) ? 0 : 1;        // use_self branch
    int nsAll = g_cnt[srcSide][b][cls];
    int sLo = (nsAll * half) >> 1;
    int sHi = (nsAll * (half + 1)) >> 1;

    const float4* __restrict__ tFeat = (const float4*)g_normc[0][b][g_off[0][b][cls]];
    const float4* __restrict__ sFeat = (const float4*)g_normc[srcSide][b][g_off[srcSide][b][cls]];
    const float4* __restrict__ sCol  = &g_colc[srcSide][b][g_off[srcSide][b][cls]];

    int tid = threadIdx.x, w = tid >> 5, lane = tid & 31;

    // TT fill: 32 targets x 64 quads, LOG2E folded; STS conflict-free
#pragma unroll
    for (int k = 0; k < 16; k++) {
        int idx = tid + 128 * k;
        int row = idx & 31, q = idx >> 5;
        int ti = min(t0 + row, nt - 1);
        float4 f = tFeat[(size_t)ti * 64 + q];
        TT4[q][row] = make_float4(f.x * LOG2E, f.y * LOG2E, f.z * LOG2E, f.w * LOG2E);
    }

    float lv[TPW], xv[TPW], yv[TPW], zv[TPW];
#pragma unroll
    for (int t = 0; t < TPW; t++) { lv[t] = 0.f; xv[t] = 0.f; yv[t] = 0.f; zv[t] = 0.f; }

    for (int c0 = sLo; c0 < sHi; c0 += 64) {
        __syncthreads();                 // prev chunk consumed (also TT ready)
        // ST fill: 64 sources x 64 quads; row-major STS, conflict-free
#pragma unroll
        for (int k = 0; k < 32; k++) {
            int idx = tid + 128 * k;
            int row = idx & 63, q = idx >> 6;
            int si = min(c0 + row, sHi - 1);
            ST4[q][row] = sFeat[(size_t)si * 64 + q];
        }
        __syncthreads();

        int n = sHi - c0;
        bool on0 = lane < n, on1 = lane + 32 < n;
        float4 sc0 = sCol[min(c0 + lane, sHi - 1)];
        float4 sc1 = sCol[min(c0 + 32 + lane, sHi - 1)];

        ull d0[TPW], d1[TPW];
#pragma unroll
        for (int t = 0; t < TPW; t++) { d0[t] = 0; d1[t] = 0; }
#pragma unroll 4
        for (int k4 = 0; k4 < 64; k4++) {
            ulonglong2 s0 = *(const ulonglong2*)&ST4[k4][lane];
            ulonglong2 s1 = *(const ulonglong2*)&ST4[k4][lane + 32];
#pragma unroll
            for (int t = 0; t < TPW; t++) {
                ulonglong2 tv = *(const ulonglong2*)&TT4[k4][TPW * w + t];
                fma2(d0[t], s0.x, tv.x);
                fma2(d0[t], s0.y, tv.y);
                fma2(d1[t], s1.x, tv.x);
                fma2(d1[t], s1.y, tv.y);
            }
        }
#pragma unroll
        for (int t = 0; t < TPW; t++) {
            float2 e0 = unpk(d0[t]), e1 = unpk(d1[t]);
            float p0 = on0 ? ex2(e0.x + e0.y) : 0.f;
            float p1 = on1 ? ex2(e1.x + e1.y) : 0.f;
            lv[t] += p0 + p1;
            xv[t] += p0 * sc0.x + p1 * sc1.x;
            yv[t] += p0 * sc0.y + p1 * sc1.y;
            zv[t] += p0 * sc0.z + p1 * sc1.z;
        }
    }

#pragma unroll
    for (int t = 0; t < TPW; t++) {
        float l = lv[t], x = xv[t], y = yv[t], z = zv[t];
#pragma unroll
        for (int off = 16; off; off >>= 1) {
            l += __shfl_xor_sync(0xffffffffu, l, off);
            x += __shfl_xor_sync(0xffffffffu, x, off);
            y += __shfl_xor_sync(0xffffffffu, y, off);
            z += __shfl_xor_sync(0xffffffffu, z, off);
        }
        int ti = t0 + TPW * w + t;
        if (lane == 0 && ti < nt)
            g_part[half][b][cls][ti] = make_float4(x, y, z, l);
    }
}

// ---------------- K6: combine partials, divide, scatter ----------------------
__global__ void k_fin()
{
    int cls = blockIdx.y + 1, b = blockIdx.z;
    int ti = blockIdx.x * blockDim.x + threadIdx.x;
    int nt = g_cnt[0][b][cls];
    if (ti >= nt) return;
    float4 pa = g_part[0][b][cls][ti];
    float4 pb = g_part[1][b][cls][ti];
    float inv = 1.f / (pa.w + pb.w);
    int tp = g_list[0][b][cls][ti];
    g_canvas[b][0][tp] = (pa.x + pb.x) * inv;
    g_canvas[b][1][tp] = (pa.y + pb.y) * inv;
    g_canvas[b][2][tp] = (pa.z + pb.z) * inv;
}

// ---------------- K7: bilinear 64->256 upsample + clip -----------------------
__global__ void k_up(float* __restrict__ out)
{
    int idx = blockIdx.x * blockDim.x + threadIdx.x;
    if (idx >= BATCH * 3 * HI * HI) return;
    int ox = idx & 255;
    int oy = (idx >> 8) & 255;
    int bc = idx >> 16;
    int c = bc % 3, b = bc / 3;
    float sy = oy * 0.25f - 0.375f;
    float sx = ox * 0.25f - 0.375f;
    int iy = (int)floorf(sy), ix = (int)floorf(sx);
    float wy = sy - (float)iy, wx = sx - (float)ix;
    int ya = max(iy, 0), yb = min(iy + 1, HS - 1);
    int xa = max(ix, 0), xb = min(ix + 1, HS - 1);
    const float* __restrict__ P = g_canvas[b][c];
    float v00 = P[ya * HS + xa], v01 = P[ya * HS + xb];
    float v10 = P[yb * HS + xa], v11 = P[yb * HS + xb];
    float v = (1.f - wy) * ((1.f - wx) * v00 + wx * v01)
            +        wy  * ((1.f - wx) * v10 + wx * v11);
    out[idx] = fminf(fmaxf(v, -1.f), 1.f);
}

// ---------------- launch -----------------------------------------------------
extern "C" void kernel_launch(void* const* d_in, const int* in_sizes, int n_in,
                              void* d_out, int out_size)
{
    const float* src_rgb = (const float*)d_in[0];
    const float* tgt_rgb = (const float*)d_in[1];
    const float* src_oh  = (const float*)d_in[2];
    const float* tgt_oh  = (const float*)d_in[3];
    const float* t_feat  = (const float*)d_in[4];
    const float* s_feat  = (const float*)d_in[5];
    float* out = (float*)d_out;

    cudaFuncSetAttribute(k_attn, cudaFuncAttributeMaxDynamicSharedMemorySize, ATTN_SMEM);

    k_pre<<<dim3(HW / 256, BATCH), 256>>>(tgt_rgb, src_rgb);
    k_compact<<<2 * BATCH, 256>>>(tgt_oh, src_oh);
    k_mean<<<dim3(CDIM / 8, BATCH, 2), 256>>>(t_feat, s_feat);
    k_tn<<<dim3(HW / 32, BATCH, 2), 256>>>(t_feat, s_feat);
    k_attn<<<dim3(HW / TGTB, NCH - 1, 2 * BATCH), 128, ATTN_SMEM>>>();
    k_fin<<<dim3(HW / 256, NCH - 1, BATCH), 256>>>();
    k_up<<<(BATCH * 3 * HI * HI) / 256, 256>>>(out);
}

// round 11
// speedup vs baseline: 1.4804x; 1.2126x over previous
#include <cuda_runtime.h>
#include <math.h>

#define BATCH 2
#define NCH   8
#define HI    256
#define HS    64
#define HW    4096
#define CDIM  256
#define LOG2E 1.4426950408889634f

typedef unsigned long long ull;

// ---------------- scratch ----------------------------------------------------
__device__ float  g_normc[2][BATCH][HW][CDIM];   // normalized, class-compacted
__device__ float4 g_colP[2][BATCH][HW];          // colors by pixel
__device__ float4 g_colc[2][BATCH][HW];          // colors compacted
__device__ int    g_lab[2][BATCH][HW];
__device__ int    g_slot[2][BATCH][HW];          // local slot within class
__device__ int    g_list[2][BATCH][NCH][HW];     // pixel list per class
__device__ int    g_cnt[2][BATCH][NCH];
__device__ int    g_off[2][BATCH][NCH];          // class prefix offsets
__device__ float  g_mean[2][BATCH][NCH][CDIM];
__device__ float4 g_part[2][BATCH][NCH][HW];     // per-half (x,y,z,l) partials
__device__ float  g_canvas[BATCH][3][HW];

__device__ __forceinline__ void fma2(ull &d, ull a, ull b) {
    asm("fma.rn.f32x2 %0, %1, %2, %0;" : "+l"(d) : "l"(a), "l"(b));
}
__device__ __forceinline__ float2 unpk(ull v) {
    float2 r; asm("mov.b64 {%0,%1}, %2;" : "=f"(r.x), "=f"(r.y) : "l"(v)); return r;
}
__device__ __forceinline__ float ex2(float x) {
    float r; asm("ex2.approx.f32 %0, %1;" : "=f"(r) : "f"(x)); return r;
}

// ---------------- K1: labels + colors + zero canvas --------------------------
__global__ void k_pre(const float* __restrict__ toh, const float* __restrict__ soh,
                      const float* __restrict__ trgb, const float* __restrict__ srgb)
{
    int pix = blockIdx.x * blockDim.x + threadIdx.x;
    int b = blockIdx.y;
    if (pix >= HW) return;
    int y4 = (pix >> 6) * 4, x4 = (pix & 63) * 4;
    int tl = 0, sl = 0;
#pragma unroll
    for (int ch = 0; ch < NCH; ch++) {
        size_t o = ((size_t)(b * NCH + ch) * HI + y4) * HI + x4;
        if (toh[o] > 0.f) tl = ch;
        if (soh[o] > 0.f) sl = ch;
    }
    g_lab[0][b][pix] = tl;
    g_lab[1][b][pix] = sl;
    float tc[3], sc[3];
#pragma unroll
    for (int ch = 0; ch < 3; ch++) {
        size_t base = ((size_t)(b * 3 + ch) * HI + (y4 + 1)) * HI + (x4 + 1);
        tc[ch] = 0.25f * (trgb[base] + trgb[base + 1] + trgb[base + HI] + trgb[base + HI + 1]);
        sc[ch] = 0.25f * (srgb[base] + srgb[base + 1] + srgb[base + HI] + srgb[base + HI + 1]);
    }
    g_colP[0][b][pix] = make_float4(tc[0], tc[1], tc[2], 0.f);
    g_colP[1][b][pix] = make_float4(sc[0], sc[1], sc[2], 0.f);
    g_canvas[b][0][pix] = 0.f;
    g_canvas[b][1][pix] = 0.f;
    g_canvas[b][2][pix] = 0.f;
}

// ---------------- K2: ballot-only compaction (lists, slots, counts, offsets) -
__global__ void k_compact()
{
    __shared__ int cnt_sm[NCH];
    int side = blockIdx.x >> 1, b = blockIdx.x & 1;
    int tid = threadIdx.x;
    int cls = tid >> 5, lane = tid & 31;
    const int4* __restrict__ lp = (const int4*)g_lab[side][b];
    int* __restrict__ lst = g_list[side][b][cls];
    int* __restrict__ slt = g_slot[side][b];
    int base = 0;
    for (int r = 0; r < HW / 128; r++) {
        int4 v = lp[r * 32 + lane];
        int vv[4] = {v.x, v.y, v.z, v.w};
#pragma unroll
        for (int e = 0; e < 4; e++) {
            bool m = (vv[e] == cls);
            unsigned bal = __ballot_sync(0xffffffffu, m);
            if (m) {
                int s = base + __popc(bal & ((1u << lane) - 1u));
                int pp = (r * 32 + lane) * 4 + e;
                lst[s] = pp;
                slt[pp] = s;
            }
            base += __popc(bal);
        }
    }
    if (lane == 0) { g_cnt[side][b][cls] = base; cnt_sm[cls] = base; }
    __syncthreads();
    if (tid == 0) {
        int off = 0;
#pragma unroll
        for (int c = 0; c < NCH; c++) { g_off[side][b][c] = off; off += cnt_sm[c]; }
    }
}

// ---------------- K3: per-class channel means (predicated accumulate) --------
__global__ void k_mean(const float* __restrict__ tfeat, const float* __restrict__ sfeat)
{
    __shared__ int lab_sm[HW];
    int b = blockIdx.y, side = blockIdx.z;
    const float* __restrict__ in = side ? sfeat : tfeat;
    int tid = threadIdx.x;
    for (int i = tid; i < HW / 4; i += 256)
        ((int4*)lab_sm)[i] = ((const int4*)g_lab[side][b])[i];
    __syncthreads();
    int ch = blockIdx.x * 8 + (tid >> 5);
    int lane = tid & 31;
    const float4* __restrict__ row = (const float4*)(in + ((size_t)b * CDIM + ch) * HW);
    float acc[7];
#pragma unroll
    for (int c = 0; c < 7; c++) acc[c] = 0.f;
    for (int it = 0; it < HW / 128; it++) {
        int i4 = it * 32 + lane;
        float4 v = row[i4];
        int4 lb = ((const int4*)lab_sm)[i4];
        float vv[4] = {v.x, v.y, v.z, v.w};
        int ll[4] = {lb.x, lb.y, lb.z, lb.w};
#pragma unroll
        for (int e = 0; e < 4; e++)
#pragma unroll
            for (int c = 0; c < 7; c++)
                acc[c] += (ll[e] == c + 1) ? vv[e] : 0.f;
    }
#pragma unroll
    for (int c = 0; c < 7; c++) {
        float s = acc[c];
#pragma unroll
        for (int off = 16; off; off >>= 1) s += __shfl_xor_sync(0xffffffffu, s, off);
        if (lane == 0)
            g_mean[side][b][c + 1][ch] = s / (float)max(g_cnt[side][b][c + 1], 1);
    }
}

// ---------------- K4: transpose + center + normalize + compact (1 smem pass) -
__global__ void k_tn(const float* __restrict__ tfeat, const float* __restrict__ sfeat)
{
    __shared__ float T[CDIM][33];
    __shared__ float MS[NCH][257];
    __shared__ int LB[32], SL[32], OFF[NCH], CNTS[NCH];

    int b = blockIdx.y, side = blockIdx.z;
    int pix0 = blockIdx.x * 32;
    const float* __restrict__ in = side ? sfeat : tfeat;
    int tid = threadIdx.x;

#pragma unroll
    for (int c = 0; c < NCH; c++)
        MS[c][tid] = (c >= 1) ? g_mean[side][b][c][tid] : 0.f;
    if (tid < 32) {
        LB[tid] = g_lab[side][b][pix0 + tid];
        SL[tid] = g_slot[side][b][pix0 + tid];
    }
    if (tid < NCH) {
        OFF[tid] = g_off[side][b][tid];
        CNTS[tid] = g_cnt[side][b][tid];
    }

    int px = tid & 31, cg = tid >> 5;
#pragma unroll
    for (int r = 0; r < 32; r++) {
        int ch = cg * 32 + r;
        T[ch][px] = in[((size_t)b * CDIM + ch) * HW + pix0 + px];
    }
    __syncthreads();

    if (tid < 32 && LB[tid] > 0)
        g_colc[side][b][OFF[LB[tid]] + SL[tid]] = g_colP[side][b][pix0 + tid];

    int px2 = tid >> 3, p = tid & 7;
    int lab = LB[px2];
    float v[32];
    float sq = 0.f;
#pragma unroll
    for (int r = 0; r < 8; r++) {
        int q = p + 8 * r;
#pragma unroll
        for (int j = 0; j < 4; j++) {
            float d = T[4 * q + j][px2] - MS[lab][4 * q + j];
            v[4 * r + j] = d;
            sq += d * d;
        }
    }
    sq += __shfl_xor_sync(0xffffffffu, sq, 1);
    sq += __shfl_xor_sync(0xffffffffu, sq, 2);
    sq += __shfl_xor_sync(0xffffffffu, sq, 4);
    float scale = (CNTS[lab] == 1) ? 1.f : 1.f / fmaxf(sqrtf(sq), 1e-12f);

    if (lab > 0) {
        float4* __restrict__ orow = (float4*)g_normc[side][b][OFF[lab] + SL[px2]];
#pragma unroll
        for (int r = 0; r < 8; r++)
            orow[p + 8 * r] = make_float4(v[4 * r] * scale, v[4 * r + 1] * scale,
                                          v[4 * r + 2] * scale, v[4 * r + 3] * scale);
    }
}

// ---------------- K5: attention (4 warps x 8 targets, 64-src chunks, --------
//          2 sources/lane, coalesced fills, ~100 KB smem -> 2 blocks/SM) -----
#define TGTB 32
#define TPW  8
#define SPAD 65
#define TPAD 33
#define ST_BYTES (64 * SPAD * 16)   // 66,560
#define TT_BYTES (64 * TPAD * 16)   // 33,792
#define ATTN_SMEM (ST_BYTES + TT_BYTES + 256)

__global__ void __launch_bounds__(128) k_attn()
{
    extern __shared__ unsigned char smem_raw[];
    float4 (*ST4)[SPAD] = (float4(*)[SPAD])(smem_raw);
    float4 (*TT4)[TPAD] = (float4(*)[TPAD])(smem_raw + ST_BYTES);

    int cls  = blockIdx.y + 1;
    int half = blockIdx.z & 1;
    int b    = blockIdx.z >> 1;
    int nt = g_cnt[0][b][cls];
    int t0 = blockIdx.x * TGTB;
    if (t0 >= nt) return;

    int scnt = g_cnt[1][b][cls];
    int srcSide = (scnt < 9) ? 0 : 1;        // use_self branch
    int nsAll = g_cnt[srcSide][b][cls];
    int sLo = (nsAll * half) >> 1;
    int sHi = (nsAll * (half + 1)) >> 1;

    const float4* __restrict__ tFeat = (const float4*)g_normc[0][b][g_off[0][b][cls]];
    const float4* __restrict__ sFeat = (const float4*)g_normc[srcSide][b][g_off[srcSide][b][cls]];
    const float4* __restrict__ sCol  = &g_colc[srcSide][b][g_off[srcSide][b][cls]];

    int tid = threadIdx.x, w = tid >> 5, lane = tid & 31;

    // TT fill: 32 targets x 64 quads; consecutive threads -> consecutive quads
    // (coalesced LDG, conflict-free STS with pad 33)
#pragma unroll
    for (int k = 0; k < 16; k++) {
        int idx = tid + 128 * k;
        int q = idx & 63, row = idx >> 6;     // row 0..31
        int ti = min(t0 + row, nt - 1);
        float4 f = tFeat[(size_t)ti * 64 + q];
        TT4[q][row] = make_float4(f.x * LOG2E, f.y * LOG2E, f.z * LOG2E, f.w * LOG2E);
    }

    float lv[TPW], xv[TPW], yv[TPW], zv[TPW];
#pragma unroll
    for (int t = 0; t < TPW; t++) { lv[t] = 0.f; xv[t] = 0.f; yv[t] = 0.f; zv[t] = 0.f; }

    for (int c0 = sLo; c0 < sHi; c0 += 64) {
        __syncthreads();                 // prev chunk consumed (also TT ready)
        // ST fill: 64 sources x 64 quads; coalesced LDG, conflict-free STS
#pragma unroll
        for (int k = 0; k < 32; k++) {
            int idx = tid + 128 * k;
            int q = idx & 63, row = idx >> 6; // row 0..63
            int si = min(c0 + row, sHi - 1);
            ST4[q][row] = sFeat[(size_t)si * 64 + q];
        }
        __syncthreads();

        int n = sHi - c0;
        bool on0 = lane < n, on1 = lane + 32 < n;
        float4 sc0 = sCol[min(c0 + lane, sHi - 1)];
        float4 sc1 = sCol[min(c0 + 32 + lane, sHi - 1)];

        ull d0[TPW], d1[TPW];
#pragma unroll
        for (int t = 0; t < TPW; t++) { d0[t] = 0; d1[t] = 0; }
#pragma unroll 4
        for (int k4 = 0; k4 < 64; k4++) {
            ulonglong2 s0 = *(const ulonglong2*)&ST4[k4][lane];
            ulonglong2 s1 = *(const ulonglong2*)&ST4[k4][lane + 32];
#pragma unroll
            for (int t = 0; t < TPW; t++) {
                ulonglong2 tv = *(const ulonglong2*)&TT4[k4][TPW * w + t];
                fma2(d0[t], s0.x, tv.x);
                fma2(d0[t], s0.y, tv.y);
                fma2(d1[t], s1.x, tv.x);
                fma2(d1[t], s1.y, tv.y);
            }
        }
#pragma unroll
        for (int t = 0; t < TPW; t++) {
            float2 e0 = unpk(d0[t]), e1 = unpk(d1[t]);
            float p0 = on0 ? ex2(e0.x + e0.y) : 0.f;
            float p1 = on1 ? ex2(e1.x + e1.y) : 0.f;
            lv[t] += p0 + p1;
            xv[t] += p0 * sc0.x + p1 * sc1.x;
            yv[t] += p0 * sc0.y + p1 * sc1.y;
            zv[t] += p0 * sc0.z + p1 * sc1.z;
        }
    }

#pragma unroll
    for (int t = 0; t < TPW; t++) {
        float l = lv[t], x = xv[t], y = yv[t], z = zv[t];
#pragma unroll
        for (int off = 16; off; off >>= 1) {
            l += __shfl_xor_sync(0xffffffffu, l, off);
            x += __shfl_xor_sync(0xffffffffu, x, off);
            y += __shfl_xor_sync(0xffffffffu, y, off);
            z += __shfl_xor_sync(0xffffffffu, z, off);
        }
        int ti = t0 + TPW * w + t;
        if (lane == 0 && ti < nt)
            g_part[half][b][cls][ti] = make_float4(x, y, z, l);
    }
}

// ---------------- K6: combine partials, divide, scatter ----------------------
__global__ void k_fin()
{
    int cls = blockIdx.y + 1, b = blockIdx.z;
    int ti = blockIdx.x * blockDim.x + threadIdx.x;
    int nt = g_cnt[0][b][cls];
    if (ti >= nt) return;
    float4 pa = g_part[0][b][cls][ti];
    float4 pb = g_part[1][b][cls][ti];
    float inv = 1.f / (pa.w + pb.w);
    int tp = g_list[0][b][cls][ti];
    g_canvas[b][0][tp] = (pa.x + pb.x) * inv;
    g_canvas[b][1][tp] = (pa.y + pb.y) * inv;
    g_canvas[b][2][tp] = (pa.z + pb.z) * inv;
}

// ---------------- K7: bilinear 64->256 upsample + clip -----------------------
__global__ void k_up(float* __restrict__ out)
{
    int idx = blockIdx.x * blockDim.x + threadIdx.x;
    if (idx >= BATCH * 3 * HI * HI) return;
    int ox = idx & 255;
    int oy = (idx >> 8) & 255;
    int bc = idx >> 16;
    int c = bc % 3, b = bc / 3;
    float sy = oy * 0.25f - 0.375f;
    float sx = ox * 0.25f - 0.375f;
    int iy = (int)floorf(sy), ix = (int)floorf(sx);
    float wy = sy - (float)iy, wx = sx - (float)ix;
    int ya = max(iy, 0), yb = min(iy + 1, HS - 1);
    int xa = max(ix, 0), xb = min(ix + 1, HS - 1);
    const float* __restrict__ P = g_canvas[b][c];
    float v00 = P[ya * HS + xa], v01 = P[ya * HS + xb];
    float v10 = P[yb * HS + xa], v11 = P[yb * HS + xb];
    float v = (1.f - wy) * ((1.f - wx) * v00 + wx * v01)
            +        wy  * ((1.f - wx) * v10 + wx * v11);
    out[idx] = fminf(fmaxf(v, -1.f), 1.f);
}

// ---------------- launch -----------------------------------------------------
extern "C" void kernel_launch(void* const* d_in, const int* in_sizes, int n_in,
                              void* d_out, int out_size)
{
    const float* src_rgb = (const float*)d_in[0];
    const float* tgt_rgb = (const float*)d_in[1];
    const float* src_oh  = (const float*)d_in[2];
    const float* tgt_oh  = (const float*)d_in[3];
    const float* t_feat  = (const float*)d_in[4];
    const float* s_feat  = (const float*)d_in[5];
    float* out = (float*)d_out;

    cudaFuncSetAttribute(k_attn, cudaFuncAttributeMaxDynamicSharedMemorySize, ATTN_SMEM);

    k_pre<<<dim3(HW / 256, BATCH), 256>>>(tgt_oh, src_oh, tgt_rgb, src_rgb);
    k_compact<<<2 * BATCH, 256>>>();
    k_mean<<<dim3(CDIM / 8, BATCH, 2), 256>>>(t_feat, s_feat);
    k_tn<<<dim3(HW / 32, BATCH, 2), 256>>>(t_feat, s_feat);
    k_attn<<<dim3(HW / TGTB, NCH - 1, 2 * BATCH), 128, ATTN_SMEM>>>();
    k_fin<<<dim3(HW / 256, NCH - 1, BATCH), 256>>>();
    k_up<<<(BATCH * 3 * HI * HI) / 256, 256>>>(out);
}